// round 7
// baseline (speedup 1.0000x reference)
#include <cuda_runtime.h>
#include <cuda_bf16.h>

namespace {
constexpr int B_ = 4, N_ = 1024, C_ = 1024, H_ = 16, D_ = 64;
constexpr float SCALE_ = 0.125f;  // 64^-0.5
}

// ---------------------------------------------------------------------------
// Scratch (__device__ globals: allocation-free rule)
// ---------------------------------------------------------------------------
__device__ float          g_S  [(size_t)B_ * H_ * N_ * N_];      // 256 MB fp32 pre-softmax scores
__device__ __nv_bfloat16  g_xqs[(size_t)4096 * 3072];            // xq split (A-role: hi,lo,hi)
__device__ __nv_bfloat16  g_xks[(size_t)4096 * 3072];
__device__ __nv_bfloat16  g_Wqs[(size_t)1024 * 3072];            // W splits (B-role: hi,hi,lo)
__device__ __nv_bfloat16  g_Wkvs[(size_t)2048 * 3072];
__device__ __nv_bfloat16  g_Wps[(size_t)1024 * 3072];
__device__ __nv_bfloat16  g_Qs [(size_t)4096 * 3072];            // Q split  (A-role)
__device__ __nv_bfloat16  g_KVs[(size_t)4096 * 6144];            // KV split (B-role, block width 2048)
__device__ __nv_bfloat16  g_Ps [(size_t)64 * 1024 * 3072];       // P split  (A-role)
__device__ __nv_bfloat16  g_Vt [(size_t)64 * 64 * 3072];         // V^T split per (b,h) (B-role)
__device__ __nv_bfloat16  g_Xs [(size_t)4096 * 3072];            // X split  (A-role)

// ---------------------------------------------------------------------------
// helpers
// ---------------------------------------------------------------------------
__device__ __forceinline__ unsigned smem_u32(const void* p) {
    unsigned a;
    asm("{ .reg .u64 t; cvta.to.shared.u64 t, %1; cvt.u32.u64 %0, t; }" : "=r"(a) : "l"(p));
    return a;
}
__device__ __forceinline__ void ldsm4(unsigned& r0, unsigned& r1, unsigned& r2, unsigned& r3,
                                      unsigned addr) {
    asm volatile("ldmatrix.sync.aligned.m8n8.x4.shared.b16 {%0,%1,%2,%3}, [%4];"
                 : "=r"(r0), "=r"(r1), "=r"(r2), "=r"(r3) : "r"(addr));
}
__device__ __forceinline__ void mma16816(float* c, const unsigned* a, const unsigned* b) {
    asm volatile(
        "mma.sync.aligned.m16n8k16.row.col.f32.bf16.bf16.f32 "
        "{%0,%1,%2,%3}, {%4,%5,%6,%7}, {%8,%9}, {%0,%1,%2,%3};"
        : "+f"(c[0]), "+f"(c[1]), "+f"(c[2]), "+f"(c[3])
        : "r"(a[0]), "r"(a[1]), "r"(a[2]), "r"(a[3]), "r"(b[0]), "r"(b[1]));
}
__device__ __forceinline__ void cpa16(unsigned dst, const void* src) {
    asm volatile("cp.async.cg.shared.global [%0], [%1], 16;" :: "r"(dst), "l"(src));
}
__device__ __forceinline__ void cpa_commit() {
    asm volatile("cp.async.commit_group;" ::: "memory");
}
__device__ __forceinline__ void cpa_wait2() {
    asm volatile("cp.async.wait_group 2;" ::: "memory");
}

// ---------------------------------------------------------------------------
// bf16 NT GEMM via mma.sync, cp.async 4-stage pipelined (1 barrier/chunk).
// M-tile 128, N-tile 64, K chunks of 64. A'[m,k'], B'[n,k'] K-major bf16.
// chunk c -> col = (c / cpb) * blkC + (c % cpb) * 64 + h * hmul
// modes: 0 fp32 store (*alpha); 1 A-split bf16 (hi,lo,hi @ +0,+bw,+2bw);
//        2 B-split bf16 (hi,hi,lo); 3 fp32 transpose store + bias (final out)
// ---------------------------------------------------------------------------
constexpr int LDSH = 72;                       // padded smem row stride (halves)
constexpr int ASZ = 128 * LDSH * 2;            // 18432 B
constexpr int BSZ = 64 * LDSH * 2;             // 9216 B
constexpr int STG = ASZ + BSZ;                 // 27648 B per stage
constexpr int STAGES = 4;
constexpr int SMEM_BYTES = STAGES * STG;       // 110592 B

__global__ __launch_bounds__(256, 2)
void mm_mma_kernel(
    const __nv_bfloat16* __restrict__ A, int lda, size_t a_bstride, size_t a_zstride,
    int a_cpb, int a_blkC, int a_hmul,
    const __nv_bfloat16* __restrict__ Bm, int ldb, size_t b_bstride, size_t b_zstride,
    int b_cpb, int b_blkC, int b_hmul,
    float* __restrict__ Cf, __nv_bfloat16* __restrict__ Cb, int ldc,
    size_t c_bstride, size_t c_zstride, int c_hmul, int c_bw,
    int nk, int mode, float alpha, const float* __restrict__ bias, int zH)
{
    constexpr int BN = 64, WN = 16, NF = 2;    // 8 warps: 2 (m) x 4 (n)
    extern __shared__ __align__(16) char dsm[];

    const int tid = threadIdx.x, lane = tid & 31, wid = tid >> 5;
    const int wm = wid & 1, wn = wid >> 1;
    const int z = blockIdx.z, b = z / zH, h = z % zH;
    const int bm = blockIdx.y * 128, bn = blockIdx.x * BN;

    const __nv_bfloat16* Ab = A + (size_t)b * a_bstride + (size_t)z * a_zstride;
    const __nv_bfloat16* Bb = Bm + (size_t)b * b_bstride + (size_t)z * b_zstride;

    const unsigned sm_u = smem_u32(dsm);

    float acc[4][NF][4];
#pragma unroll
    for (int i = 0; i < 4; i++)
#pragma unroll
        for (int j = 0; j < NF; j++)
#pragma unroll
            for (int e = 0; e < 4; e++) acc[i][j][e] = 0.f;

    // ldmatrix lane->row/col
    const int a_row_l = (lane & 7) + ((lane >> 3) & 1) * 8;
    const int a_col_l = (lane >> 4) * 8;
    const int b_row_l = (lane & 7) + (lane >> 4) * 8;
    const int b_col_l = ((lane >> 3) & 1) * 8;

    // async load of chunk c into stage s
    auto issue = [&](int c, int s) {
        const int acol = (c / a_cpb) * a_blkC + (c % a_cpb) * 64 + h * a_hmul;
        const int bcol = (c / b_cpb) * b_blkC + (c % b_cpb) * 64 + h * b_hmul;
        const unsigned baseA = sm_u + s * STG;
        const unsigned baseB = baseA + ASZ;
#pragma unroll
        for (int i = 0; i < 4; i++) {
            const int idx = tid + i * 256;
            const int r = idx >> 3, q = idx & 7;
            cpa16(baseA + (r * LDSH + q * 8) * 2,
                  Ab + (size_t)(bm + r) * lda + acol + q * 8);
        }
#pragma unroll
        for (int i = 0; i < 2; i++) {
            const int idx = tid + i * 256;
            const int r = idx >> 3, q = idx & 7;
            cpa16(baseB + (r * LDSH + q * 8) * 2,
                  Bb + (size_t)(bn + r) * ldb + bcol + q * 8);
        }
    };

    // prologue: fill STAGES-1 stages
#pragma unroll
    for (int s = 0; s < STAGES - 1; s++) {
        if (s < nk) issue(s, s);
        cpa_commit();
    }

    for (int c = 0; c < nk; c++) {
        cpa_wait2();          // chunk c resident (<=2 younger groups pending)
        __syncthreads();      // all threads see stage c; stage (c-1)%4 fully consumed

        const int nx = c + STAGES - 1;
        if (nx < nk) issue(nx, nx & (STAGES - 1));
        cpa_commit();

        const unsigned baseA = sm_u + (c & (STAGES - 1)) * STG;
        const unsigned baseB = baseA + ASZ;
#pragma unroll
        for (int kk = 0; kk < 4; kk++) {
            unsigned af[4][4];
            unsigned bf[NF][2];
#pragma unroll
            for (int mi = 0; mi < 4; mi++) {
                const unsigned addr =
                    baseA + ((wm * 64 + mi * 16 + a_row_l) * LDSH + kk * 16 + a_col_l) * 2;
                ldsm4(af[mi][0], af[mi][1], af[mi][2], af[mi][3], addr);
            }
            {
                const unsigned addr =
                    baseB + ((wn * WN + b_row_l) * LDSH + kk * 16 + b_col_l) * 2;
                ldsm4(bf[0][0], bf[0][1], bf[1][0], bf[1][1], addr);
            }
#pragma unroll
            for (int mi = 0; mi < 4; mi++)
#pragma unroll
                for (int nf = 0; nf < NF; nf++)
                    mma16816(acc[mi][nf], af[mi], bf[nf]);
        }
    }
    __syncthreads();   // protect stage smem before epilogue reuse

    // Epilogue: stage 128x32 fp32 through smem (pad 33) for coalesced stores.
    float* ep = reinterpret_cast<float*>(dsm);
    float* Cfb = Cf ? Cf + (size_t)b * c_bstride + (size_t)z * c_zstride : nullptr;
    __nv_bfloat16* Cbb = Cb ? Cb + (size_t)b * c_bstride + (size_t)z * c_zstride : nullptr;
    const int colbase0 = bn + h * c_hmul;

    for (int nb = 0; nb < BN; nb += 32) {
#pragma unroll
        for (int mi = 0; mi < 4; mi++)
#pragma unroll
            for (int nf = 0; nf < NF; nf++) {
                const int gcol = wn * WN + nf * 8;
                if (gcol >= nb && gcol < nb + 32) {
                    const int lc = gcol - nb;
                    const int r0 = wm * 64 + mi * 16 + (lane >> 2);
                    const int cc = lc + (lane & 3) * 2;
                    ep[r0 * 33 + cc]           = acc[mi][nf][0];
                    ep[r0 * 33 + cc + 1]       = acc[mi][nf][1];
                    ep[(r0 + 8) * 33 + cc]     = acc[mi][nf][2];
                    ep[(r0 + 8) * 33 + cc + 1] = acc[mi][nf][3];
                }
            }
        __syncthreads();
        const int row = tid >> 1, c0 = (tid & 1) * 16;
        const int gr = bm + row;
        const int gc = colbase0 + nb + c0;
        float vv[16];
#pragma unroll
        for (int j = 0; j < 16; j++) vv[j] = ep[row * 33 + c0 + j] * alpha;
        if (mode == 0) {
            float* o = Cfb + (size_t)gr * ldc + gc;
#pragma unroll
            for (int j = 0; j < 16; j++) o[j] = vv[j];
        } else if (mode == 1 || mode == 2) {
            __nv_bfloat16* o = Cbb + (size_t)gr * ldc + gc;
#pragma unroll
            for (int j = 0; j < 16; j++) {
                __nv_bfloat16 hi = __float2bfloat16(vv[j]);
                __nv_bfloat16 lo = __float2bfloat16(vv[j] - __bfloat162float(hi));
                if (mode == 1) { o[j] = hi; o[c_bw + j] = lo; o[2 * c_bw + j] = hi; }
                else           { o[j] = hi; o[c_bw + j] = hi; o[2 * c_bw + j] = lo; }
            }
        } else {  // mode 3: out1[(nq*B + b)*C + n] = v + bias
            const int bo = gr >> 10, nq = gr & 1023;
            float* o = Cf + ((size_t)nq * B_ + bo) * C_ + gc;
#pragma unroll
            for (int j = 0; j < 16; j++) o[j] = vv[j] + bias[gc + j];
        }
        __syncthreads();
    }
}

// ---------------------------------------------------------------------------
// fp32 -> bf16 split. brole=0: (hi,lo,hi); brole=1: (hi,hi,lo). grid (K/256, R)
// ---------------------------------------------------------------------------
__global__ __launch_bounds__(256)
void split_kernel(const float* __restrict__ in, __nv_bfloat16* __restrict__ out,
                  int K, int brole)
{
    const int k = blockIdx.x * 256 + threadIdx.x;
    const int r = blockIdx.y;
    const float x = in[(size_t)r * K + k];
    const __nv_bfloat16 hi = __float2bfloat16(x);
    const __nv_bfloat16 lo = __float2bfloat16(x - __bfloat162float(hi));
    __nv_bfloat16* o = out + (size_t)r * 3 * K;
    if (brole) { o[k] = hi; o[K + k] = hi; o[2 * K + k] = lo; }
    else       { o[k] = hi; o[K + k] = lo; o[2 * K + k] = hi; }
}

// ---------------------------------------------------------------------------
// Fused: out2 accumulation (pre-softmax head mean) + row softmax + P' split.
// One block per (b,q); loops over 16 heads; S read exactly once.
// ---------------------------------------------------------------------------
__global__ __launch_bounds__(256)
void fuse_ms_kernel(const float* __restrict__ S, float* __restrict__ out2,
                    __nv_bfloat16* __restrict__ P)
{
    __shared__ float smax[8];
    __shared__ float ssum[8];
    const int tid = threadIdx.x;
    const int bq = blockIdx.x;                   // b*1024 + q
    const int b = bq >> 10, q = bq & 1023;

    float am0 = 0.f, am1 = 0.f, am2 = 0.f, am3 = 0.f;

    for (int h = 0; h < H_; h++) {
        const size_t rz = ((size_t)(b * H_ + h) << 10) + q;   // (b,h,q) row index
        const float* row = S + rz * N_;
        float4 v = reinterpret_cast<const float4*>(row)[tid];
        am0 += v.x; am1 += v.y; am2 += v.z; am3 += v.w;

        float m = fmaxf(fmaxf(v.x, v.y), fmaxf(v.z, v.w));
#pragma unroll
        for (int o = 16; o > 0; o >>= 1) m = fmaxf(m, __shfl_xor_sync(0xffffffffu, m, o));
        if ((tid & 31) == 0) smax[tid >> 5] = m;
        __syncthreads();
        float rm = smax[0];
#pragma unroll
        for (int i = 1; i < 8; i++) rm = fmaxf(rm, smax[i]);

        float e0 = __expf(v.x - rm), e1 = __expf(v.y - rm);
        float e2 = __expf(v.z - rm), e3 = __expf(v.w - rm);
        float s = e0 + e1 + e2 + e3;
#pragma unroll
        for (int o = 16; o > 0; o >>= 1) s += __shfl_xor_sync(0xffffffffu, s, o);
        if ((tid & 31) == 0) ssum[tid >> 5] = s;
        __syncthreads();
        float rs = ssum[0];
#pragma unroll
        for (int i = 1; i < 8; i++) rs += ssum[i];
        const float inv = __frcp_rn(rs);

        float vals[4] = {e0 * inv, e1 * inv, e2 * inv, e3 * inv};
        __nv_bfloat16* o = P + rz * 3072 + tid * 4;
#pragma unroll
        for (int e = 0; e < 4; e++) {
            __nv_bfloat16 hi = __float2bfloat16(vals[e]);
            __nv_bfloat16 lo = __float2bfloat16(vals[e] - __bfloat162float(hi));
            o[e] = hi; o[1024 + e] = lo; o[2048 + e] = hi;
        }
        __syncthreads();   // protect smax/ssum reuse next h
    }

    float4 ov = make_float4(am0 * (1.0f / H_), am1 * (1.0f / H_),
                            am2 * (1.0f / H_), am3 * (1.0f / H_));
    reinterpret_cast<float4*>(out2)[(size_t)bq * 256 + tid] = ov;
}

// ---------------------------------------------------------------------------
// Vt'[z][d, :] = V^T split (B-role hi,hi,lo) from KV'. grid (16 ktile, 64 z)
// ---------------------------------------------------------------------------
__global__ __launch_bounds__(256)
void transpose_v_kernel(const __nv_bfloat16* __restrict__ KVs, __nv_bfloat16* __restrict__ Vt)
{
    __shared__ __nv_bfloat16 hi[64][72];
    __shared__ __nv_bfloat16 lo[64][72];
    const int tid = threadIdx.x;
    const int z = blockIdx.y, bb = z >> 4, h = z & 15, kt = blockIdx.x;
    const __nv_bfloat16* base = KVs + (size_t)(bb * 1024 + kt * 64) * 6144;
    for (int i = tid; i < 512; i += 256) {
        const int r = i >> 3, c8 = i & 7;
        uint4 vh = *reinterpret_cast<const uint4*>(base + (size_t)r * 6144 + 1024 + h * 64 + c8 * 8);
        uint4 vl = *reinterpret_cast<const uint4*>(base + (size_t)r * 6144 + 5120 + h * 64 + c8 * 8);
        *reinterpret_cast<uint4*>(&hi[r][c8 * 8]) = vh;
        *reinterpret_cast<uint4*>(&lo[r][c8 * 8]) = vl;
    }
    __syncthreads();
    __nv_bfloat16* out = Vt + (size_t)z * 64 * 3072;
    for (int i = tid; i < 512; i += 256) {
        const int d = i >> 3, c8 = i & 7;
        __nv_bfloat16 th[8], tl[8];
#pragma unroll
        for (int e = 0; e < 8; e++) { th[e] = hi[c8 * 8 + e][d]; tl[e] = lo[c8 * 8 + e][d]; }
        __nv_bfloat16* o = out + (size_t)d * 3072 + kt * 64 + c8 * 8;
        *reinterpret_cast<uint4*>(o)        = *reinterpret_cast<uint4*>(th);
        *reinterpret_cast<uint4*>(o + 1024) = *reinterpret_cast<uint4*>(th);
        *reinterpret_cast<uint4*>(o + 2048) = *reinterpret_cast<uint4*>(tl);
    }
}

// ---------------------------------------------------------------------------
extern "C" void kernel_launch(void* const* d_in, const int* in_sizes, int n_in,
                              void* d_out, int out_size)
{
    const float* xq  = (const float*)d_in[0];
    const float* xk  = (const float*)d_in[1];
    const float* Wq  = (const float*)d_in[3];
    const float* Wkv = (const float*)d_in[4];
    const float* Wp  = (const float*)d_in[5];
    const float* bp  = (const float*)d_in[6];

    float* out1 = (float*)d_out;                      // [N, B, C]
    float* out2 = out1 + (size_t)N_ * B_ * C_;        // [B, N, N]

    float* S;
    __nv_bfloat16 *xqs, *xks, *Wqs, *Wkvs, *Wps, *Qs, *KVs, *Ps, *Vt, *Xs;
    cudaGetSymbolAddress((void**)&S,    g_S);
    cudaGetSymbolAddress((void**)&xqs,  g_xqs);
    cudaGetSymbolAddress((void**)&xks,  g_xks);
    cudaGetSymbolAddress((void**)&Wqs,  g_Wqs);
    cudaGetSymbolAddress((void**)&Wkvs, g_Wkvs);
    cudaGetSymbolAddress((void**)&Wps,  g_Wps);
    cudaGetSymbolAddress((void**)&Qs,   g_Qs);
    cudaGetSymbolAddress((void**)&KVs,  g_KVs);
    cudaGetSymbolAddress((void**)&Ps,   g_Ps);
    cudaGetSymbolAddress((void**)&Vt,   g_Vt);
    cudaGetSymbolAddress((void**)&Xs,   g_Xs);

    cudaFuncSetAttribute(mm_mma_kernel,
                         cudaFuncAttributeMaxDynamicSharedMemorySize, SMEM_BYTES);

    // Launch order keeps index 3 = Q-projection GEMM (ncu capture hook).
    split_kernel<<<dim3(4, 4096), 256>>>(xq,  xqs,  1024, 0);
    split_kernel<<<dim3(4, 1024), 256>>>(Wq,  Wqs,  1024, 1);
    split_kernel<<<dim3(4, 4096), 256>>>(xk,  xks,  1024, 0);

    // 3) Q' = (xq @ Wq^T) split : M=4096, N=1024, K'=3072 (48 chunks)  [PROFILED]
    mm_mma_kernel<<<dim3(16, 32, 1), 256, SMEM_BYTES>>>(
        xqs, 3072, 0, 0, 16, 1024, 0,
        Wqs, 3072, 0, 0, 16, 1024, 0,
        nullptr, Qs, 3072, 0, 0, 0, 1024,
        48, 1, 1.0f, nullptr, 1);

    split_kernel<<<dim3(4, 2048), 256>>>(Wkv, Wkvs, 1024, 1);
    split_kernel<<<dim3(4, 1024), 256>>>(Wp,  Wps,  1024, 1);

    // KV' = (xk @ Wkv^T) split (B-role) : M=4096, N=2048
    mm_mma_kernel<<<dim3(32, 32, 1), 256, SMEM_BYTES>>>(
        xks, 3072, 0, 0, 16, 1024, 0,
        Wkvs, 3072, 0, 0, 16, 1024, 0,
        nullptr, KVs, 6144, 0, 0, 0, 2048,
        48, 2, 1.0f, nullptr, 1);

    // V^T split
    transpose_v_kernel<<<dim3(16, 64), 256>>>(KVs, Vt);

    // S = SCALE * Q K^T per (b,h) : M=1024, N=1024, K'=192 (3 chunks)
    mm_mma_kernel<<<dim3(16, 8, 64), 256, SMEM_BYTES>>>(
        Qs, 3072, (size_t)1024 * 3072, 0, 1, 1024, 64,
        KVs, 6144, (size_t)1024 * 6144, 0, 1, 2048, 64,
        S, nullptr, 1024, 0, (size_t)N_ * N_, 0, 0,
        3, 0, SCALE_, nullptr, 16);

    // fused: out2 head-mean + softmax + P' split (S read once)
    fuse_ms_kernel<<<B_ * N_, 256>>>(S, out2, Ps);

    // X' = (P @ V) split per (b,h) : M=1024, N=64, K'=3072
    mm_mma_kernel<<<dim3(1, 8, 64), 256, SMEM_BYTES>>>(
        Ps, 3072, 0, (size_t)1024 * 3072, 16, 1024, 0,
        Vt, 3072, 0, (size_t)64 * 3072, 16, 1024, 0,
        nullptr, Xs, 3072, (size_t)1024 * 3072, 0, 64, 1024,
        48, 1, 1.0f, nullptr, 16);

    // out1 = (X @ Wp^T + bp) transposed store [nq, b, c]
    mm_mma_kernel<<<dim3(16, 32, 1), 256, SMEM_BYTES>>>(
        Xs, 3072, 0, 0, 16, 1024, 0,
        Wps, 3072, 0, 0, 16, 1024, 0,
        out1, nullptr, 1024, 0, 0, 0, 0,
        48, 3, 1.0f, bp, 1);
}

// round 8
// speedup vs baseline: 1.0457x; 1.0457x over previous
#include <cuda_runtime.h>
#include <cuda_bf16.h>

namespace {
constexpr int B_ = 4, N_ = 1024, C_ = 1024, H_ = 16, D_ = 64;
constexpr float SCALE_ = 0.125f;  // 64^-0.5
}

// ---------------------------------------------------------------------------
// Scratch (__device__ globals: allocation-free rule)
// ---------------------------------------------------------------------------
__device__ float          g_S  [(size_t)B_ * H_ * N_ * N_];      // 256 MB fp32 pre-softmax scores
__device__ __nv_bfloat16  g_xqs[(size_t)4096 * 3072];            // xq split (A-role: hi,lo,hi)
__device__ __nv_bfloat16  g_xks[(size_t)4096 * 3072];
__device__ __nv_bfloat16  g_Wqs[(size_t)1024 * 3072];            // W splits (B-role: hi,hi,lo)
__device__ __nv_bfloat16  g_Wkvs[(size_t)2048 * 3072];
__device__ __nv_bfloat16  g_Wps[(size_t)1024 * 3072];
__device__ __nv_bfloat16  g_Qs [(size_t)4096 * 3072];            // Q split  (A-role)
__device__ __nv_bfloat16  g_KVs[(size_t)4096 * 6144];            // KV split (B-role, block width 2048)
__device__ __nv_bfloat16  g_Ps [(size_t)64 * 1024 * 3072];       // P split  (A-role)
__device__ __nv_bfloat16  g_Vt [(size_t)64 * 64 * 3072];         // V^T split per (b,h) (B-role)
__device__ __nv_bfloat16  g_Xs [(size_t)4096 * 3072];            // X split  (A-role)

// ---------------------------------------------------------------------------
// helpers
// ---------------------------------------------------------------------------
__device__ __forceinline__ unsigned smem_u32(const void* p) {
    unsigned a;
    asm("{ .reg .u64 t; cvta.to.shared.u64 t, %1; cvt.u32.u64 %0, t; }" : "=r"(a) : "l"(p));
    return a;
}
__device__ __forceinline__ void ldsm4(unsigned& r0, unsigned& r1, unsigned& r2, unsigned& r3,
                                      unsigned addr) {
    asm volatile("ldmatrix.sync.aligned.m8n8.x4.shared.b16 {%0,%1,%2,%3}, [%4];"
                 : "=r"(r0), "=r"(r1), "=r"(r2), "=r"(r3) : "r"(addr));
}
__device__ __forceinline__ void mma16816(float* c, const unsigned* a, const unsigned* b) {
    asm volatile(
        "mma.sync.aligned.m16n8k16.row.col.f32.bf16.bf16.f32 "
        "{%0,%1,%2,%3}, {%4,%5,%6,%7}, {%8,%9}, {%0,%1,%2,%3};"
        : "+f"(c[0]), "+f"(c[1]), "+f"(c[2]), "+f"(c[3])
        : "r"(a[0]), "r"(a[1]), "r"(a[2]), "r"(a[3]), "r"(b[0]), "r"(b[1]));
}
__device__ __forceinline__ void cpa16(unsigned dst, const void* src) {
    asm volatile("cp.async.cg.shared.global [%0], [%1], 16;" :: "r"(dst), "l"(src));
}
__device__ __forceinline__ void cpa_commit() {
    asm volatile("cp.async.commit_group;" ::: "memory");
}
__device__ __forceinline__ void cpa_wait2() {
    asm volatile("cp.async.wait_group 2;" ::: "memory");
}

// ---------------------------------------------------------------------------
// bf16 NT GEMM via mma.sync, cp.async 4-stage + fragment double-buffering.
// M-tile 128, N-tile 64, K chunks of 64. 8 warps in 4(m) x 2(n); warp tile 32x32.
// chunk c -> col advances incrementally: +64 within a cpb-block, then jump.
// modes: 0 fp32 store (*alpha); 1 A-split bf16 (hi,lo,hi @ +0,+bw,+2bw);
//        2 B-split bf16 (hi,hi,lo); 3 fp32 transpose store + bias (final out)
// ---------------------------------------------------------------------------
constexpr int LDSH = 72;                       // padded smem row stride (halves)
constexpr int ASZ = 128 * LDSH * 2;            // 18432 B
constexpr int BSZ = 64 * LDSH * 2;             // 9216 B
constexpr int STG = ASZ + BSZ;                 // 27648 B per stage
constexpr int STAGES = 4;
constexpr int SMEM_BYTES = STAGES * STG;       // 110592 B

__global__ __launch_bounds__(256, 2)
void mm_mma_kernel(
    const __nv_bfloat16* __restrict__ A, int lda, size_t a_bstride, size_t a_zstride,
    int a_cpb, int a_blkC, int a_hmul,
    const __nv_bfloat16* __restrict__ Bm, int ldb, size_t b_bstride, size_t b_zstride,
    int b_cpb, int b_blkC, int b_hmul,
    float* __restrict__ Cf, __nv_bfloat16* __restrict__ Cb, int ldc,
    size_t c_bstride, size_t c_zstride, int c_hmul, int c_bw,
    int nk, int mode, float alpha, const float* __restrict__ bias, int zH)
{
    constexpr int BN = 64;
    extern __shared__ __align__(16) char dsm[];

    const int tid = threadIdx.x, lane = tid & 31, wid = tid >> 5;
    const int wm = wid >> 1, wn = wid & 1;     // 4 x 2 warp grid, warp tile 32x32
    const int z = blockIdx.z, b = z / zH, h = z % zH;
    const int bm = blockIdx.y * 128, bn = blockIdx.x * BN;

    const __nv_bfloat16* Ab = A + (size_t)b * a_bstride + (size_t)z * a_zstride;
    const __nv_bfloat16* Bb = Bm + (size_t)b * b_bstride + (size_t)z * b_zstride;

    const unsigned sm_u = smem_u32(dsm);

    float acc[2][4][4];
#pragma unroll
    for (int i = 0; i < 2; i++)
#pragma unroll
        for (int j = 0; j < 4; j++)
#pragma unroll
            for (int e = 0; e < 4; e++) acc[i][j][e] = 0.f;

    // ldmatrix lane->row/col
    const int a_row_l = (lane & 7) + ((lane >> 3) & 1) * 8;
    const int a_col_l = (lane >> 4) * 8;
    const int b_row_l = (lane & 7) + (lane >> 4) * 8;
    const int b_col_l = ((lane >> 3) & 1) * 8;

    // incremental column state for the prefetch (issue) stream
    int ia_col = h * a_hmul, ib_col = h * b_hmul;
    int ia_cnt = 0, ib_cnt = 0;
    auto issue = [&](int s) {
        const unsigned baseA = sm_u + s * STG;
        const unsigned baseB = baseA + ASZ;
#pragma unroll
        for (int i = 0; i < 4; i++) {
            const int idx = tid + i * 256;
            const int r = idx >> 3, q = idx & 7;
            cpa16(baseA + (r * LDSH + q * 8) * 2,
                  Ab + (size_t)(bm + r) * lda + ia_col + q * 8);
        }
#pragma unroll
        for (int i = 0; i < 2; i++) {
            const int idx = tid + i * 256;
            const int r = idx >> 3, q = idx & 7;
            cpa16(baseB + (r * LDSH + q * 8) * 2,
                  Bb + (size_t)(bn + r) * ldb + ib_col + q * 8);
        }
        if (++ia_cnt == a_cpb) { ia_cnt = 0; ia_col += a_blkC - (a_cpb - 1) * 64; }
        else ia_col += 64;
        if (++ib_cnt == b_cpb) { ib_cnt = 0; ib_col += b_blkC - (b_cpb - 1) * 64; }
        else ib_col += 64;
    };

    // prologue: fill STAGES-1 stages
#pragma unroll
    for (int s = 0; s < STAGES - 1; s++) {
        if (s < nk) issue(s);
        cpa_commit();
    }

    unsigned af[2][2][4];   // [buf][mi][4]
    unsigned bf[2][4][2];   // [buf][nf][2]

    for (int c = 0; c < nk; c++) {
        cpa_wait2();          // chunk c resident
        __syncthreads();      // stage (c-1)%4 fully consumed

        const int nx = c + STAGES - 1;
        if (nx < nk) issue(nx & (STAGES - 1));
        cpa_commit();

        const unsigned baseA = sm_u + (c & (STAGES - 1)) * STG;
        const unsigned baseB = baseA + ASZ;

        // load kk=0 fragments into buffer 0
#pragma unroll
        for (int mi = 0; mi < 2; mi++)
            ldsm4(af[0][mi][0], af[0][mi][1], af[0][mi][2], af[0][mi][3],
                  baseA + ((wm * 32 + mi * 16 + a_row_l) * LDSH + a_col_l) * 2);
#pragma unroll
        for (int p = 0; p < 2; p++)
            ldsm4(bf[0][2 * p][0], bf[0][2 * p][1], bf[0][2 * p + 1][0], bf[0][2 * p + 1][1],
                  baseB + ((wn * 32 + p * 16 + b_row_l) * LDSH + b_col_l) * 2);

#pragma unroll
        for (int kk = 0; kk < 4; kk++) {
            const int cu = kk & 1, nb2 = cu ^ 1;
            if (kk < 3) {   // prefetch next k-step fragments before MMAs
                const int kc = (kk + 1) * 16;
#pragma unroll
                for (int mi = 0; mi < 2; mi++)
                    ldsm4(af[nb2][mi][0], af[nb2][mi][1], af[nb2][mi][2], af[nb2][mi][3],
                          baseA + ((wm * 32 + mi * 16 + a_row_l) * LDSH + kc + a_col_l) * 2);
#pragma unroll
                for (int p = 0; p < 2; p++)
                    ldsm4(bf[nb2][2 * p][0], bf[nb2][2 * p][1],
                          bf[nb2][2 * p + 1][0], bf[nb2][2 * p + 1][1],
                          baseB + ((wn * 32 + p * 16 + b_row_l) * LDSH + kc + b_col_l) * 2);
            }
#pragma unroll
            for (int mi = 0; mi < 2; mi++)
#pragma unroll
                for (int nf = 0; nf < 4; nf++)
                    mma16816(acc[mi][nf], af[cu][mi], bf[cu][nf]);
        }
    }
    __syncthreads();   // protect stage smem before epilogue reuse

    // Epilogue: stage 128x32 fp32 through smem (pad 33) for coalesced stores.
    float* ep = reinterpret_cast<float*>(dsm);
    float* Cfb = Cf ? Cf + (size_t)b * c_bstride + (size_t)z * c_zstride : nullptr;
    __nv_bfloat16* Cbb = Cb ? Cb + (size_t)b * c_bstride + (size_t)z * c_zstride : nullptr;
    const int colbase0 = bn + h * c_hmul;

    for (int nb = 0; nb < BN; nb += 32) {
        if (wn == (nb >> 5)) {
#pragma unroll
            for (int mi = 0; mi < 2; mi++)
#pragma unroll
                for (int nf = 0; nf < 4; nf++) {
                    const int lc = nf * 8;
                    const int r0 = wm * 32 + mi * 16 + (lane >> 2);
                    const int cc = lc + (lane & 3) * 2;
                    ep[r0 * 33 + cc]           = acc[mi][nf][0];
                    ep[r0 * 33 + cc + 1]       = acc[mi][nf][1];
                    ep[(r0 + 8) * 33 + cc]     = acc[mi][nf][2];
                    ep[(r0 + 8) * 33 + cc + 1] = acc[mi][nf][3];
                }
        }
        __syncthreads();
        const int row = tid >> 1, c0 = (tid & 1) * 16;
        const int gr = bm + row;
        const int gc = colbase0 + nb + c0;
        float vv[16];
#pragma unroll
        for (int j = 0; j < 16; j++) vv[j] = ep[row * 33 + c0 + j] * alpha;
        if (mode == 0) {
            float* o = Cfb + (size_t)gr * ldc + gc;
#pragma unroll
            for (int j = 0; j < 16; j++) o[j] = vv[j];
        } else if (mode == 1 || mode == 2) {
            __nv_bfloat16* o = Cbb + (size_t)gr * ldc + gc;
#pragma unroll
            for (int j = 0; j < 16; j++) {
                __nv_bfloat16 hi = __float2bfloat16(vv[j]);
                __nv_bfloat16 lo = __float2bfloat16(vv[j] - __bfloat162float(hi));
                if (mode == 1) { o[j] = hi; o[c_bw + j] = lo; o[2 * c_bw + j] = hi; }
                else           { o[j] = hi; o[c_bw + j] = hi; o[2 * c_bw + j] = lo; }
            }
        } else {  // mode 3: out1[(nq*B + b)*C + n] = v + bias
            const int bo = gr >> 10, nq = gr & 1023;
            float* o = Cf + ((size_t)nq * B_ + bo) * C_ + gc;
#pragma unroll
            for (int j = 0; j < 16; j++) o[j] = vv[j] + bias[gc + j];
        }
        __syncthreads();
    }
}

// ---------------------------------------------------------------------------
// fp32 -> bf16 split. brole=0: (hi,lo,hi); brole=1: (hi,hi,lo). grid (K/256, R)
// ---------------------------------------------------------------------------
__global__ __launch_bounds__(256)
void split_kernel(const float* __restrict__ in, __nv_bfloat16* __restrict__ out,
                  int K, int brole)
{
    const int k = blockIdx.x * 256 + threadIdx.x;
    const int r = blockIdx.y;
    const float x = in[(size_t)r * K + k];
    const __nv_bfloat16 hi = __float2bfloat16(x);
    const __nv_bfloat16 lo = __float2bfloat16(x - __bfloat162float(hi));
    __nv_bfloat16* o = out + (size_t)r * 3 * K;
    if (brole) { o[k] = hi; o[K + k] = hi; o[2 * K + k] = lo; }
    else       { o[k] = hi; o[K + k] = lo; o[2 * K + k] = hi; }
}

// ---------------------------------------------------------------------------
// Fused: out2 accumulation (pre-softmax head mean) + row softmax + P' split.
// One block per (b,q); loops over 16 heads; S read exactly once.
// ---------------------------------------------------------------------------
__global__ __launch_bounds__(256)
void fuse_ms_kernel(const float* __restrict__ S, float* __restrict__ out2,
                    __nv_bfloat16* __restrict__ P)
{
    __shared__ float smax[8];
    __shared__ float ssum[8];
    const int tid = threadIdx.x;
    const int bq = blockIdx.x;                   // b*1024 + q
    const int b = bq >> 10, q = bq & 1023;

    float am0 = 0.f, am1 = 0.f, am2 = 0.f, am3 = 0.f;

    for (int h = 0; h < H_; h++) {
        const size_t rz = ((size_t)(b * H_ + h) << 10) + q;   // (b,h,q) row index
        const float* row = S + rz * N_;
        float4 v = reinterpret_cast<const float4*>(row)[tid];
        am0 += v.x; am1 += v.y; am2 += v.z; am3 += v.w;

        float m = fmaxf(fmaxf(v.x, v.y), fmaxf(v.z, v.w));
#pragma unroll
        for (int o = 16; o > 0; o >>= 1) m = fmaxf(m, __shfl_xor_sync(0xffffffffu, m, o));
        if ((tid & 31) == 0) smax[tid >> 5] = m;
        __syncthreads();
        float rm = smax[0];
#pragma unroll
        for (int i = 1; i < 8; i++) rm = fmaxf(rm, smax[i]);

        float e0 = __expf(v.x - rm), e1 = __expf(v.y - rm);
        float e2 = __expf(v.z - rm), e3 = __expf(v.w - rm);
        float s = e0 + e1 + e2 + e3;
#pragma unroll
        for (int o = 16; o > 0; o >>= 1) s += __shfl_xor_sync(0xffffffffu, s, o);
        if ((tid & 31) == 0) ssum[tid >> 5] = s;
        __syncthreads();
        float rs = ssum[0];
#pragma unroll
        for (int i = 1; i < 8; i++) rs += ssum[i];
        const float inv = __frcp_rn(rs);

        float vals[4] = {e0 * inv, e1 * inv, e2 * inv, e3 * inv};
        __nv_bfloat16* o = P + rz * 3072 + tid * 4;
#pragma unroll
        for (int e = 0; e < 4; e++) {
            __nv_bfloat16 hi = __float2bfloat16(vals[e]);
            __nv_bfloat16 lo = __float2bfloat16(vals[e] - __bfloat162float(hi));
            o[e] = hi; o[1024 + e] = lo; o[2048 + e] = hi;
        }
        __syncthreads();   // protect smax/ssum reuse next h
    }

    float4 ov = make_float4(am0 * (1.0f / H_), am1 * (1.0f / H_),
                            am2 * (1.0f / H_), am3 * (1.0f / H_));
    reinterpret_cast<float4*>(out2)[(size_t)bq * 256 + tid] = ov;
}

// ---------------------------------------------------------------------------
// Vt'[z][d, :] = V^T split (B-role hi,hi,lo) from KV'. grid (16 ktile, 64 z)
// ---------------------------------------------------------------------------
__global__ __launch_bounds__(256)
void transpose_v_kernel(const __nv_bfloat16* __restrict__ KVs, __nv_bfloat16* __restrict__ Vt)
{
    __shared__ __nv_bfloat16 hi[64][72];
    __shared__ __nv_bfloat16 lo[64][72];
    const int tid = threadIdx.x;
    const int z = blockIdx.y, bb = z >> 4, h = z & 15, kt = blockIdx.x;
    const __nv_bfloat16* base = KVs + (size_t)(bb * 1024 + kt * 64) * 6144;
    for (int i = tid; i < 512; i += 256) {
        const int r = i >> 3, c8 = i & 7;
        uint4 vh = *reinterpret_cast<const uint4*>(base + (size_t)r * 6144 + 1024 + h * 64 + c8 * 8);
        uint4 vl = *reinterpret_cast<const uint4*>(base + (size_t)r * 6144 + 5120 + h * 64 + c8 * 8);
        *reinterpret_cast<uint4*>(&hi[r][c8 * 8]) = vh;
        *reinterpret_cast<uint4*>(&lo[r][c8 * 8]) = vl;
    }
    __syncthreads();
    __nv_bfloat16* out = Vt + (size_t)z * 64 * 3072;
    for (int i = tid; i < 512; i += 256) {
        const int d = i >> 3, c8 = i & 7;
        __nv_bfloat16 th[8], tl[8];
#pragma unroll
        for (int e = 0; e < 8; e++) { th[e] = hi[c8 * 8 + e][d]; tl[e] = lo[c8 * 8 + e][d]; }
        __nv_bfloat16* o = out + (size_t)d * 3072 + kt * 64 + c8 * 8;
        *reinterpret_cast<uint4*>(o)        = *reinterpret_cast<uint4*>(th);
        *reinterpret_cast<uint4*>(o + 1024) = *reinterpret_cast<uint4*>(th);
        *reinterpret_cast<uint4*>(o + 2048) = *reinterpret_cast<uint4*>(tl);
    }
}

// ---------------------------------------------------------------------------
extern "C" void kernel_launch(void* const* d_in, const int* in_sizes, int n_in,
                              void* d_out, int out_size)
{
    const float* xq  = (const float*)d_in[0];
    const float* xk  = (const float*)d_in[1];
    const float* Wq  = (const float*)d_in[3];
    const float* Wkv = (const float*)d_in[4];
    const float* Wp  = (const float*)d_in[5];
    const float* bp  = (const float*)d_in[6];

    float* out1 = (float*)d_out;                      // [N, B, C]
    float* out2 = out1 + (size_t)N_ * B_ * C_;        // [B, N, N]

    float* S;
    __nv_bfloat16 *xqs, *xks, *Wqs, *Wkvs, *Wps, *Qs, *KVs, *Ps, *Vt, *Xs;
    cudaGetSymbolAddress((void**)&S,    g_S);
    cudaGetSymbolAddress((void**)&xqs,  g_xqs);
    cudaGetSymbolAddress((void**)&xks,  g_xks);
    cudaGetSymbolAddress((void**)&Wqs,  g_Wqs);
    cudaGetSymbolAddress((void**)&Wkvs, g_Wkvs);
    cudaGetSymbolAddress((void**)&Wps,  g_Wps);
    cudaGetSymbolAddress((void**)&Qs,   g_Qs);
    cudaGetSymbolAddress((void**)&KVs,  g_KVs);
    cudaGetSymbolAddress((void**)&Ps,   g_Ps);
    cudaGetSymbolAddress((void**)&Vt,   g_Vt);
    cudaGetSymbolAddress((void**)&Xs,   g_Xs);

    cudaFuncSetAttribute(mm_mma_kernel,
                         cudaFuncAttributeMaxDynamicSharedMemorySize, SMEM_BYTES);

    // Launch order keeps index 3 = Q-projection GEMM (ncu capture hook).
    split_kernel<<<dim3(4, 4096), 256>>>(xq,  xqs,  1024, 0);
    split_kernel<<<dim3(4, 1024), 256>>>(Wq,  Wqs,  1024, 1);
    split_kernel<<<dim3(4, 4096), 256>>>(xk,  xks,  1024, 0);

    // 3) Q' = (xq @ Wq^T) split : M=4096, N=1024, K'=3072 (48 chunks)  [PROFILED]
    mm_mma_kernel<<<dim3(16, 32, 1), 256, SMEM_BYTES>>>(
        xqs, 3072, 0, 0, 16, 1024, 0,
        Wqs, 3072, 0, 0, 16, 1024, 0,
        nullptr, Qs, 3072, 0, 0, 0, 1024,
        48, 1, 1.0f, nullptr, 1);

    split_kernel<<<dim3(4, 2048), 256>>>(Wkv, Wkvs, 1024, 1);
    split_kernel<<<dim3(4, 1024), 256>>>(Wp,  Wps,  1024, 1);

    // KV' = (xk @ Wkv^T) split (B-role) : M=4096, N=2048
    mm_mma_kernel<<<dim3(32, 32, 1), 256, SMEM_BYTES>>>(
        xks, 3072, 0, 0, 16, 1024, 0,
        Wkvs, 3072, 0, 0, 16, 1024, 0,
        nullptr, KVs, 6144, 0, 0, 0, 2048,
        48, 2, 1.0f, nullptr, 1);

    // V^T split
    transpose_v_kernel<<<dim3(16, 64), 256>>>(KVs, Vt);

    // S = SCALE * Q K^T per (b,h) : M=1024, N=1024, K'=192 (3 chunks)
    mm_mma_kernel<<<dim3(16, 8, 64), 256, SMEM_BYTES>>>(
        Qs, 3072, (size_t)1024 * 3072, 0, 1, 1024, 64,
        KVs, 6144, (size_t)1024 * 6144, 0, 1, 2048, 64,
        S, nullptr, 1024, 0, (size_t)N_ * N_, 0, 0,
        3, 0, SCALE_, nullptr, 16);

    // fused: out2 head-mean + softmax + P' split (S read once)
    fuse_ms_kernel<<<B_ * N_, 256>>>(S, out2, Ps);

    // X' = (P @ V) split per (b,h) : M=1024, N=64, K'=3072
    mm_mma_kernel<<<dim3(1, 8, 64), 256, SMEM_BYTES>>>(
        Ps, 3072, 0, (size_t)1024 * 3072, 16, 1024, 0,
        Vt, 3072, 0, (size_t)64 * 3072, 16, 1024, 0,
        nullptr, Xs, 3072, (size_t)1024 * 3072, 0, 64, 1024,
        48, 1, 1.0f, nullptr, 16);

    // out1 = (X @ Wp^T + bp) transposed store [nq, b, c]
    mm_mma_kernel<<<dim3(16, 32, 1), 256, SMEM_BYTES>>>(
        Xs, 3072, 0, 0, 16, 1024, 0,
        Wps, 3072, 0, 0, 16, 1024, 0,
        out1, nullptr, 1024, 0, 0, 0, 0,
        48, 3, 1.0f, bp, 1);
}

// round 9
// speedup vs baseline: 1.0744x; 1.0275x over previous
#include <cuda_runtime.h>
#include <cuda_bf16.h>

namespace {
constexpr int B_ = 4, N_ = 1024, C_ = 1024, H_ = 16, D_ = 64;
constexpr float SCALE_ = 0.125f;  // 64^-0.5
}

// ---------------------------------------------------------------------------
// Scratch (__device__ globals: allocation-free rule)
// ---------------------------------------------------------------------------
__device__ float          g_S  [(size_t)B_ * H_ * N_ * N_];      // 256 MB fp32 pre-softmax scores
__device__ __nv_bfloat16  g_xqs[(size_t)4096 * 3072];            // xq split (A-role: hi,lo,hi)
__device__ __nv_bfloat16  g_xks[(size_t)4096 * 3072];
__device__ __nv_bfloat16  g_Wqs[(size_t)1024 * 3072];            // W splits (B-role: hi,hi,lo)
__device__ __nv_bfloat16  g_Wkvs[(size_t)2048 * 3072];
__device__ __nv_bfloat16  g_Wps[(size_t)1024 * 3072];
__device__ __nv_bfloat16  g_Qs [(size_t)4096 * 3072];            // Q split  (A-role)
__device__ __nv_bfloat16  g_KVs[(size_t)4096 * 6144];            // KV split (B-role, block width 2048)
__device__ __nv_bfloat16  g_Ps [(size_t)64 * 1024 * 3072];       // P split  (A-role)
__device__ __nv_bfloat16  g_Vt [(size_t)64 * 64 * 3072];         // V^T split per (b,h) (B-role)
__device__ __nv_bfloat16  g_Xs [(size_t)4096 * 3072];            // X split  (A-role)

// ---------------------------------------------------------------------------
// helpers
// ---------------------------------------------------------------------------
__device__ __forceinline__ unsigned smem_u32(const void* p) {
    unsigned a;
    asm("{ .reg .u64 t; cvta.to.shared.u64 t, %1; cvt.u32.u64 %0, t; }" : "=r"(a) : "l"(p));
    return a;
}
__device__ __forceinline__ void ldsm4(unsigned& r0, unsigned& r1, unsigned& r2, unsigned& r3,
                                      unsigned addr) {
    asm volatile("ldmatrix.sync.aligned.m8n8.x4.shared.b16 {%0,%1,%2,%3}, [%4];"
                 : "=r"(r0), "=r"(r1), "=r"(r2), "=r"(r3) : "r"(addr));
}
__device__ __forceinline__ void mma16816(float* c, const unsigned* a, const unsigned* b) {
    asm volatile(
        "mma.sync.aligned.m16n8k16.row.col.f32.bf16.bf16.f32 "
        "{%0,%1,%2,%3}, {%4,%5,%6,%7}, {%8,%9}, {%0,%1,%2,%3};"
        : "+f"(c[0]), "+f"(c[1]), "+f"(c[2]), "+f"(c[3])
        : "r"(a[0]), "r"(a[1]), "r"(a[2]), "r"(a[3]), "r"(b[0]), "r"(b[1]));
}
__device__ __forceinline__ void cpa16(unsigned dst, const void* src) {
    asm volatile("cp.async.cg.shared.global [%0], [%1], 16;" :: "r"(dst), "l"(src));
}
__device__ __forceinline__ void cpa_commit() {
    asm volatile("cp.async.commit_group;" ::: "memory");
}
__device__ __forceinline__ void cpa_wait1() {
    asm volatile("cp.async.wait_group 1;" ::: "memory");
}

// ---------------------------------------------------------------------------
// bf16 NT GEMM via mma.sync, cp.async 3-stage, warp tile 32 x (BN/2).
// Block tile 128 x BN. 8 warps in 4(m) x 2(n). 16 acc chains/warp at BN=128.
// chunk c -> col advances incrementally (+64 within cpb-block, then jump).
// modes: 0 fp32 store (*alpha); 1 A-split bf16 (hi,lo,hi @ +0,+bw,+2bw);
//        2 B-split bf16 (hi,hi,lo); 3 fp32 transpose store + bias (final out)
// ---------------------------------------------------------------------------
constexpr int LDSH = 72;                       // padded smem row stride (halves)
constexpr int ASZ = 128 * LDSH * 2;            // 18432 B
constexpr int STAGES = 3;
template <int BN> struct SmemCfg {
    static constexpr int BSZ = BN * LDSH * 2;
    static constexpr int STG = ASZ + BSZ;
    static constexpr int BYTES = STAGES * STG;  // BN=128: 110592; BN=64: 82944
};

template <int BN>
__global__ __launch_bounds__(256, 2)
void mm_mma_kernel(
    const __nv_bfloat16* __restrict__ A, int lda, size_t a_bstride, size_t a_zstride,
    int a_cpb, int a_blkC, int a_hmul,
    const __nv_bfloat16* __restrict__ Bm, int ldb, size_t b_bstride, size_t b_zstride,
    int b_cpb, int b_blkC, int b_hmul,
    float* __restrict__ Cf, __nv_bfloat16* __restrict__ Cb, int ldc,
    size_t c_bstride, size_t c_zstride, int c_hmul, int c_bw,
    int nk, int mode, float alpha, const float* __restrict__ bias, int zH)
{
    constexpr int NF = BN / 16;                // n-frags per warp (8 @BN=128)
    constexpr int WNE = NF * 8;                // warp n-extent
    constexpr int STG = SmemCfg<BN>::STG;
    extern __shared__ __align__(16) char dsm[];

    const int tid = threadIdx.x, lane = tid & 31, wid = tid >> 5;
    const int wm = wid >> 1, wn = wid & 1;     // 4 x 2 warp grid
    const int z = blockIdx.z, b = z / zH, h = z % zH;
    const int bm = blockIdx.y * 128, bn = blockIdx.x * BN;

    const __nv_bfloat16* Ab = A + (size_t)b * a_bstride + (size_t)z * a_zstride;
    const __nv_bfloat16* Bb = Bm + (size_t)b * b_bstride + (size_t)z * b_zstride;

    const unsigned sm_u = smem_u32(dsm);

    float acc[2][NF][4];
#pragma unroll
    for (int i = 0; i < 2; i++)
#pragma unroll
        for (int j = 0; j < NF; j++)
#pragma unroll
            for (int e = 0; e < 4; e++) acc[i][j][e] = 0.f;

    // ldmatrix lane->row/col
    const int a_row_l = (lane & 7) + ((lane >> 3) & 1) * 8;
    const int a_col_l = (lane >> 4) * 8;
    const int b_row_l = (lane & 7) + (lane >> 4) * 8;
    const int b_col_l = ((lane >> 3) & 1) * 8;

    // incremental column state for the prefetch (issue) stream
    int ia_col = h * a_hmul, ib_col = h * b_hmul;
    int ia_cnt = 0, ib_cnt = 0;
    auto issue = [&](int s) {
        const unsigned baseA = sm_u + s * STG;
        const unsigned baseB = baseA + ASZ;
#pragma unroll
        for (int i = 0; i < 4; i++) {
            const int idx = tid + i * 256;
            const int r = idx >> 3, q = idx & 7;
            cpa16(baseA + (r * LDSH + q * 8) * 2,
                  Ab + (size_t)(bm + r) * lda + ia_col + q * 8);
        }
#pragma unroll
        for (int i = 0; i < BN / 32; i++) {
            const int idx = tid + i * 256;
            const int r = idx >> 3, q = idx & 7;
            cpa16(baseB + (r * LDSH + q * 8) * 2,
                  Bb + (size_t)(bn + r) * ldb + ib_col + q * 8);
        }
        if (++ia_cnt == a_cpb) { ia_cnt = 0; ia_col += a_blkC - (a_cpb - 1) * 64; }
        else ia_col += 64;
        if (++ib_cnt == b_cpb) { ib_cnt = 0; ib_col += b_blkC - (b_cpb - 1) * 64; }
        else ib_col += 64;
    };

    // prologue: fill STAGES-1 = 2 stages
#pragma unroll
    for (int s = 0; s < STAGES - 1; s++) {
        if (s < nk) issue(s);
        cpa_commit();
    }

    int stage = 0;
    for (int c = 0; c < nk; c++) {
        cpa_wait1();          // chunk c resident (<=1 younger group pending)
        __syncthreads();      // previous stage fully consumed by all warps

        if (c + STAGES - 1 < nk) {
            int s2 = stage + 2; if (s2 >= STAGES) s2 -= STAGES;
            issue(s2);
        }
        cpa_commit();

        const unsigned baseA = sm_u + stage * STG;
        const unsigned baseB = baseA + ASZ;
#pragma unroll
        for (int kk = 0; kk < 4; kk++) {
            unsigned af[2][4];
            unsigned bf[NF][2];
#pragma unroll
            for (int mi = 0; mi < 2; mi++)
                ldsm4(af[mi][0], af[mi][1], af[mi][2], af[mi][3],
                      baseA + ((wm * 32 + mi * 16 + a_row_l) * LDSH + kk * 16 + a_col_l) * 2);
#pragma unroll
            for (int p = 0; p < NF / 2; p++)
                ldsm4(bf[2 * p][0], bf[2 * p][1], bf[2 * p + 1][0], bf[2 * p + 1][1],
                      baseB + ((wn * WNE + p * 16 + b_row_l) * LDSH + kk * 16 + b_col_l) * 2);
#pragma unroll
            for (int mi = 0; mi < 2; mi++)
#pragma unroll
                for (int nf = 0; nf < NF; nf++)
                    mma16816(acc[mi][nf], af[mi], bf[nf]);
        }
        if (++stage == STAGES) stage = 0;
    }
    __syncthreads();   // protect stage smem before epilogue reuse

    // Epilogue: stage 128x32 fp32 through smem (pad 33) for coalesced stores.
    float* ep = reinterpret_cast<float*>(dsm);
    float* Cfb = Cf ? Cf + (size_t)b * c_bstride + (size_t)z * c_zstride : nullptr;
    __nv_bfloat16* Cbb = Cb ? Cb + (size_t)b * c_bstride + (size_t)z * c_zstride : nullptr;
    const int colbase0 = bn + h * c_hmul;

    for (int nb = 0; nb < BN; nb += 32) {
#pragma unroll
        for (int mi = 0; mi < 2; mi++)
#pragma unroll
            for (int nf = 0; nf < NF; nf++) {
                const int gcol = wn * WNE + nf * 8;
                if (gcol >= nb && gcol < nb + 32) {
                    const int lc = gcol - nb;
                    const int r0 = wm * 32 + mi * 16 + (lane >> 2);
                    const int cc = lc + (lane & 3) * 2;
                    ep[r0 * 33 + cc]           = acc[mi][nf][0];
                    ep[r0 * 33 + cc + 1]       = acc[mi][nf][1];
                    ep[(r0 + 8) * 33 + cc]     = acc[mi][nf][2];
                    ep[(r0 + 8) * 33 + cc + 1] = acc[mi][nf][3];
                }
            }
        __syncthreads();
        const int row = tid >> 1, c0 = (tid & 1) * 16;
        const int gr = bm + row;
        const int gc = colbase0 + nb + c0;
        float vv[16];
#pragma unroll
        for (int j = 0; j < 16; j++) vv[j] = ep[row * 33 + c0 + j] * alpha;
        if (mode == 0) {
            float* o = Cfb + (size_t)gr * ldc + gc;
#pragma unroll
            for (int j = 0; j < 16; j++) o[j] = vv[j];
        } else if (mode == 1 || mode == 2) {
            __nv_bfloat16* o = Cbb + (size_t)gr * ldc + gc;
#pragma unroll
            for (int j = 0; j < 16; j++) {
                __nv_bfloat16 hi = __float2bfloat16(vv[j]);
                __nv_bfloat16 lo = __float2bfloat16(vv[j] - __bfloat162float(hi));
                if (mode == 1) { o[j] = hi; o[c_bw + j] = lo; o[2 * c_bw + j] = hi; }
                else           { o[j] = hi; o[c_bw + j] = hi; o[2 * c_bw + j] = lo; }
            }
        } else {  // mode 3: out1[(nq*B + b)*C + n] = v + bias
            const int bo = gr >> 10, nq = gr & 1023;
            float* o = Cf + ((size_t)nq * B_ + bo) * C_ + gc;
#pragma unroll
            for (int j = 0; j < 16; j++) o[j] = vv[j] + bias[gc + j];
        }
        __syncthreads();
    }
}

// ---------------------------------------------------------------------------
// fp32 -> bf16 split. brole=0: (hi,lo,hi); brole=1: (hi,hi,lo). grid (K/256, R)
// ---------------------------------------------------------------------------
__global__ __launch_bounds__(256)
void split_kernel(const float* __restrict__ in, __nv_bfloat16* __restrict__ out,
                  int K, int brole)
{
    const int k = blockIdx.x * 256 + threadIdx.x;
    const int r = blockIdx.y;
    const float x = in[(size_t)r * K + k];
    const __nv_bfloat16 hi = __float2bfloat16(x);
    const __nv_bfloat16 lo = __float2bfloat16(x - __bfloat162float(hi));
    __nv_bfloat16* o = out + (size_t)r * 3 * K;
    if (brole) { o[k] = hi; o[K + k] = hi; o[2 * K + k] = lo; }
    else       { o[k] = hi; o[K + k] = lo; o[2 * K + k] = hi; }
}

// ---------------------------------------------------------------------------
// Fused: out2 accumulation (pre-softmax head mean) + row softmax + P' split.
// One block per (b,q); loops over 16 heads; S read exactly once.
// ---------------------------------------------------------------------------
__global__ __launch_bounds__(256)
void fuse_ms_kernel(const float* __restrict__ S, float* __restrict__ out2,
                    __nv_bfloat16* __restrict__ P)
{
    __shared__ float smax[8];
    __shared__ float ssum[8];
    const int tid = threadIdx.x;
    const int bq = blockIdx.x;                   // b*1024 + q
    const int b = bq >> 10, q = bq & 1023;

    float am0 = 0.f, am1 = 0.f, am2 = 0.f, am3 = 0.f;

    for (int h = 0; h < H_; h++) {
        const size_t rz = ((size_t)(b * H_ + h) << 10) + q;   // (b,h,q) row index
        const float* row = S + rz * N_;
        float4 v = reinterpret_cast<const float4*>(row)[tid];
        am0 += v.x; am1 += v.y; am2 += v.z; am3 += v.w;

        float m = fmaxf(fmaxf(v.x, v.y), fmaxf(v.z, v.w));
#pragma unroll
        for (int o = 16; o > 0; o >>= 1) m = fmaxf(m, __shfl_xor_sync(0xffffffffu, m, o));
        if ((tid & 31) == 0) smax[tid >> 5] = m;
        __syncthreads();
        float rm = smax[0];
#pragma unroll
        for (int i = 1; i < 8; i++) rm = fmaxf(rm, smax[i]);

        float e0 = __expf(v.x - rm), e1 = __expf(v.y - rm);
        float e2 = __expf(v.z - rm), e3 = __expf(v.w - rm);
        float s = e0 + e1 + e2 + e3;
#pragma unroll
        for (int o = 16; o > 0; o >>= 1) s += __shfl_xor_sync(0xffffffffu, s, o);
        if ((tid & 31) == 0) ssum[tid >> 5] = s;
        __syncthreads();
        float rs = ssum[0];
#pragma unroll
        for (int i = 1; i < 8; i++) rs += ssum[i];
        const float inv = __frcp_rn(rs);

        float vals[4] = {e0 * inv, e1 * inv, e2 * inv, e3 * inv};
        __nv_bfloat16* o = P + rz * 3072 + tid * 4;
#pragma unroll
        for (int e = 0; e < 4; e++) {
            __nv_bfloat16 hi = __float2bfloat16(vals[e]);
            __nv_bfloat16 lo = __float2bfloat16(vals[e] - __bfloat162float(hi));
            o[e] = hi; o[1024 + e] = lo; o[2048 + e] = hi;
        }
        __syncthreads();   // protect smax/ssum reuse next h
    }

    float4 ov = make_float4(am0 * (1.0f / H_), am1 * (1.0f / H_),
                            am2 * (1.0f / H_), am3 * (1.0f / H_));
    reinterpret_cast<float4*>(out2)[(size_t)bq * 256 + tid] = ov;
}

// ---------------------------------------------------------------------------
// Vt'[z][d, :] = V^T split (B-role hi,hi,lo) from KV'. grid (16 ktile, 64 z)
// ---------------------------------------------------------------------------
__global__ __launch_bounds__(256)
void transpose_v_kernel(const __nv_bfloat16* __restrict__ KVs, __nv_bfloat16* __restrict__ Vt)
{
    __shared__ __nv_bfloat16 hi[64][72];
    __shared__ __nv_bfloat16 lo[64][72];
    const int tid = threadIdx.x;
    const int z = blockIdx.y, bb = z >> 4, h = z & 15, kt = blockIdx.x;
    const __nv_bfloat16* base = KVs + (size_t)(bb * 1024 + kt * 64) * 6144;
    for (int i = tid; i < 512; i += 256) {
        const int r = i >> 3, c8 = i & 7;
        uint4 vh = *reinterpret_cast<const uint4*>(base + (size_t)r * 6144 + 1024 + h * 64 + c8 * 8);
        uint4 vl = *reinterpret_cast<const uint4*>(base + (size_t)r * 6144 + 5120 + h * 64 + c8 * 8);
        *reinterpret_cast<uint4*>(&hi[r][c8 * 8]) = vh;
        *reinterpret_cast<uint4*>(&lo[r][c8 * 8]) = vl;
    }
    __syncthreads();
    __nv_bfloat16* out = Vt + (size_t)z * 64 * 3072;
    for (int i = tid; i < 512; i += 256) {
        const int d = i >> 3, c8 = i & 7;
        __nv_bfloat16 th[8], tl[8];
#pragma unroll
        for (int e = 0; e < 8; e++) { th[e] = hi[c8 * 8 + e][d]; tl[e] = lo[c8 * 8 + e][d]; }
        __nv_bfloat16* o = out + (size_t)d * 3072 + kt * 64 + c8 * 8;
        *reinterpret_cast<uint4*>(o)        = *reinterpret_cast<uint4*>(th);
        *reinterpret_cast<uint4*>(o + 1024) = *reinterpret_cast<uint4*>(th);
        *reinterpret_cast<uint4*>(o + 2048) = *reinterpret_cast<uint4*>(tl);
    }
}

// ---------------------------------------------------------------------------
extern "C" void kernel_launch(void* const* d_in, const int* in_sizes, int n_in,
                              void* d_out, int out_size)
{
    const float* xq  = (const float*)d_in[0];
    const float* xk  = (const float*)d_in[1];
    const float* Wq  = (const float*)d_in[3];
    const float* Wkv = (const float*)d_in[4];
    const float* Wp  = (const float*)d_in[5];
    const float* bp  = (const float*)d_in[6];

    float* out1 = (float*)d_out;                      // [N, B, C]
    float* out2 = out1 + (size_t)N_ * B_ * C_;        // [B, N, N]

    float* S;
    __nv_bfloat16 *xqs, *xks, *Wqs, *Wkvs, *Wps, *Qs, *KVs, *Ps, *Vt, *Xs;
    cudaGetSymbolAddress((void**)&S,    g_S);
    cudaGetSymbolAddress((void**)&xqs,  g_xqs);
    cudaGetSymbolAddress((void**)&xks,  g_xks);
    cudaGetSymbolAddress((void**)&Wqs,  g_Wqs);
    cudaGetSymbolAddress((void**)&Wkvs, g_Wkvs);
    cudaGetSymbolAddress((void**)&Wps,  g_Wps);
    cudaGetSymbolAddress((void**)&Qs,   g_Qs);
    cudaGetSymbolAddress((void**)&KVs,  g_KVs);
    cudaGetSymbolAddress((void**)&Ps,   g_Ps);
    cudaGetSymbolAddress((void**)&Vt,   g_Vt);
    cudaGetSymbolAddress((void**)&Xs,   g_Xs);

    cudaFuncSetAttribute(mm_mma_kernel<128>,
                         cudaFuncAttributeMaxDynamicSharedMemorySize, SmemCfg<128>::BYTES);
    cudaFuncSetAttribute(mm_mma_kernel<64>,
                         cudaFuncAttributeMaxDynamicSharedMemorySize, SmemCfg<64>::BYTES);

    // Launch order keeps index 3 = Q-projection GEMM (ncu capture hook).
    split_kernel<<<dim3(4, 4096), 256>>>(xq,  xqs,  1024, 0);
    split_kernel<<<dim3(4, 1024), 256>>>(Wq,  Wqs,  1024, 1);
    split_kernel<<<dim3(4, 4096), 256>>>(xk,  xks,  1024, 0);

    // 3) Q' = (xq @ Wq^T) split : M=4096, N=1024, K'=3072 (48 chunks)  [PROFILED]
    mm_mma_kernel<128><<<dim3(8, 32, 1), 256, SmemCfg<128>::BYTES>>>(
        xqs, 3072, 0, 0, 16, 1024, 0,
        Wqs, 3072, 0, 0, 16, 1024, 0,
        nullptr, Qs, 3072, 0, 0, 0, 1024,
        48, 1, 1.0f, nullptr, 1);

    split_kernel<<<dim3(4, 2048), 256>>>(Wkv, Wkvs, 1024, 1);
    split_kernel<<<dim3(4, 1024), 256>>>(Wp,  Wps,  1024, 1);

    // KV' = (xk @ Wkv^T) split (B-role) : M=4096, N=2048
    mm_mma_kernel<128><<<dim3(16, 32, 1), 256, SmemCfg<128>::BYTES>>>(
        xks, 3072, 0, 0, 16, 1024, 0,
        Wkvs, 3072, 0, 0, 16, 1024, 0,
        nullptr, KVs, 6144, 0, 0, 0, 2048,
        48, 2, 1.0f, nullptr, 1);

    // V^T split
    transpose_v_kernel<<<dim3(16, 64), 256>>>(KVs, Vt);

    // S = SCALE * Q K^T per (b,h) : M=1024, N=1024, K'=192 (3 chunks)
    mm_mma_kernel<128><<<dim3(8, 8, 64), 256, SmemCfg<128>::BYTES>>>(
        Qs, 3072, (size_t)1024 * 3072, 0, 1, 1024, 64,
        KVs, 6144, (size_t)1024 * 6144, 0, 1, 2048, 64,
        S, nullptr, 1024, 0, (size_t)N_ * N_, 0, 0,
        3, 0, SCALE_, nullptr, 16);

    // fused: out2 head-mean + softmax + P' split (S read once)
    fuse_ms_kernel<<<B_ * N_, 256>>>(S, out2, Ps);

    // X' = (P @ V) split per (b,h) : M=1024, N=64, K'=3072
    mm_mma_kernel<64><<<dim3(1, 8, 64), 256, SmemCfg<64>::BYTES>>>(
        Ps, 3072, 0, (size_t)1024 * 3072, 16, 1024, 0,
        Vt, 3072, 0, (size_t)64 * 3072, 16, 1024, 0,
        nullptr, Xs, 3072, (size_t)1024 * 3072, 0, 64, 1024,
        48, 1, 1.0f, nullptr, 16);

    // out1 = (X @ Wp^T + bp) transposed store [nq, b, c]
    mm_mma_kernel<128><<<dim3(8, 32, 1), 256, SmemCfg<128>::BYTES>>>(
        Xs, 3072, 0, 0, 16, 1024, 0,
        Wps, 3072, 0, 0, 16, 1024, 0,
        out1, nullptr, 1024, 0, 0, 0, 0,
        48, 3, 1.0f, bp, 1);
}